// round 2
// baseline (speedup 1.0000x reference)
#include <cuda_runtime.h>

#define NSTEP  25
#define NIN    9
#define NHID   100

// Each batch element is handled by TWO threads (even lane: neurons 0-49,
// odd lane: neurons 50-99). Per-timestep layer-2 inputs are accumulated in
// packed f32x2 registers (out0 in lo, out1 in hi), reduced across the lane
// pair with shfl.bfly, then layer-2 LIF runs on the even lane.
__global__ __launch_bounds__(128) void snn_kernel(
    const float* __restrict__ x,
    const float* __restrict__ W1,
    const float* __restrict__ b1,
    const float* __restrict__ W2,
    const float* __restrict__ b2,
    float* __restrict__ out,
    int batch)
{
    // W1 padded to 12 floats/row: [w0..w8, b1, 0, 0] -> 3x LDS.128 per neuron
    __shared__ float4 sW1[NHID * 3];
    __shared__ unsigned long long sW2p[NHID];   // packed (W2[0][h], W2[1][h])
    __shared__ float sb2[2];

    {
        float* sW1f = (float*)sW1;
        for (int h = threadIdx.x; h < NHID; h += blockDim.x) {
#pragma unroll
            for (int i = 0; i < NIN; i++) sW1f[h * 12 + i] = W1[h * NIN + i];
            sW1f[h * 12 + 9]  = b1[h];
            sW1f[h * 12 + 10] = 0.0f;
            sW1f[h * 12 + 11] = 0.0f;
            unsigned lo = __float_as_uint(W2[h]);          // -> out 0
            unsigned hi = __float_as_uint(W2[NHID + h]);   // -> out 1
            sW2p[h] = ((unsigned long long)hi << 32) | lo;
        }
        if (threadIdx.x < 2) sb2[threadIdx.x] = b2[threadIdx.x];
    }
    __syncthreads();

    int gt   = blockIdx.x * blockDim.x + threadIdx.x;
    int b    = gt >> 1;
    int half = gt & 1;
    if (b >= batch) return;

    float xv[NIN];
#pragma unroll
    for (int i = 0; i < NIN; i++) xv[i] = __ldg(&x[(size_t)b * NIN + i]);

    unsigned long long acc[NSTEP];
#pragma unroll
    for (int t = 0; t < NSTEP; t++) acc[t] = 0ULL;

    const int hbase = half * (NHID / 2);

    for (int hh = 0; hh < NHID / 2; hh += 2) {
        const int h = hbase + hh;

        // cur1 for neurons h and h+1 (bias stored at padded slot 9 == a2.y)
        float4 a0 = sW1[h * 3 + 0], a1 = sW1[h * 3 + 1], a2 = sW1[h * 3 + 2];
        float4 d0 = sW1[(h + 1) * 3 + 0], d1 = sW1[(h + 1) * 3 + 1], d2 = sW1[(h + 1) * 3 + 2];

        float c0 = a2.y;
        c0 = fmaf(xv[0], a0.x, c0); c0 = fmaf(xv[1], a0.y, c0);
        c0 = fmaf(xv[2], a0.z, c0); c0 = fmaf(xv[3], a0.w, c0);
        c0 = fmaf(xv[4], a1.x, c0); c0 = fmaf(xv[5], a1.y, c0);
        c0 = fmaf(xv[6], a1.z, c0); c0 = fmaf(xv[7], a1.w, c0);
        c0 = fmaf(xv[8], a2.x, c0);

        float c1 = d2.y;
        c1 = fmaf(xv[0], d0.x, c1); c1 = fmaf(xv[1], d0.y, c1);
        c1 = fmaf(xv[2], d0.z, c1); c1 = fmaf(xv[3], d0.w, c1);
        c1 = fmaf(xv[4], d1.x, c1); c1 = fmaf(xv[5], d1.y, c1);
        c1 = fmaf(xv[6], d1.z, c1); c1 = fmaf(xv[7], d1.w, c1);
        c1 = fmaf(xv[8], d2.x, c1);

        const float c0m1 = c0 - 1.0f;
        const float c1m1 = c1 - 1.0f;
        unsigned long long wA = sW2p[h];
        unsigned long long wB = sW2p[h + 1];

        // m after the first membrane update (m_prev=0, reset=0): m = cur1
        float m0 = c0;
        float m1 = c1;

        // Per step (4 instr/neuron): FSETP; @p FADD.f32x2; FSEL; FFMA-imm.
        //   spike_t = (m_t > 1)   -> acc[t] += (w_out0, w_out1)
        //   m_{t+1} = beta*m_t + (spike_t ? c-1 : c)
#pragma unroll
        for (int t = 0; t < NSTEP; t++) {
            asm("{\n\t"
                ".reg .pred p;\n\t"
                ".reg .f32 cr;\n\t"
                "setp.gt.f32 p, %1, 0f3F800000;\n\t"
                "@p add.rn.f32x2 %0, %0, %2;\n\t"
                "selp.f32 cr, %3, %4, p;\n\t"
                "fma.rn.f32 %1, 0f3F733333, %1, cr;\n\t"
                "}"
                : "+l"(acc[t]), "+f"(m0)
                : "l"(wA), "f"(c0m1), "f"(c0));
            asm("{\n\t"
                ".reg .pred p;\n\t"
                ".reg .f32 cr;\n\t"
                "setp.gt.f32 p, %1, 0f3F800000;\n\t"
                "@p add.rn.f32x2 %0, %0, %2;\n\t"
                "selp.f32 cr, %3, %4, p;\n\t"
                "fma.rn.f32 %1, 0f3F733333, %1, cr;\n\t"
                "}"
                : "+l"(acc[t]), "+f"(m1)
                : "l"(wB), "f"(c1m1), "f"(c1));
        }
    }

    // Reduce the two half-sums across the lane pair (bfly -> both get total)
#pragma unroll
    for (int t = 0; t < NSTEP; t++) {
        unsigned long long o = __shfl_xor_sync(0xffffffffu, acc[t], 1);
        asm("add.rn.f32x2 %0, %0, %1;" : "+l"(acc[t]) : "l"(o));
    }

    if (half == 0) {
        const float bb0 = sb2[0], bb1 = sb2[1];
        float m20 = 0.0f, m21 = 0.0f;
        float2* outv = (float2*)out;
#pragma unroll
        for (int t = 0; t < NSTEP; t++) {
            float a0f = __uint_as_float((unsigned)(acc[t] & 0xffffffffu));
            float a1f = __uint_as_float((unsigned)(acc[t] >> 32));
            float r0 = (m20 > 1.0f) ? 1.0f : 0.0f;   // reset from PREVIOUS mem2
            float r1 = (m21 > 1.0f) ? 1.0f : 0.0f;
            m20 = fmaf(0.95f, m20, a0f + bb0) - r0;
            m21 = fmaf(0.95f, m21, a1f + bb1) - r1;
            outv[(size_t)t * batch + b] = make_float2(m20, m21);
        }
    }
}

extern "C" void kernel_launch(void* const* d_in, const int* in_sizes, int n_in,
                              void* d_out, int out_size)
{
    const float* x  = (const float*)d_in[0];
    const float* W1 = (const float*)d_in[1];
    const float* b1 = (const float*)d_in[2];
    const float* W2 = (const float*)d_in[3];
    const float* b2 = (const float*)d_in[4];
    float* out = (float*)d_out;

    int batch = in_sizes[0] / NIN;
    const int threads = 128;              // 64 batch elems per block
    int total = batch * 2;                // 2 threads per batch element
    int blocks = (total + threads - 1) / threads;
    snn_kernel<<<blocks, threads>>>(x, W1, b1, W2, b2, out, batch);
}

// round 3
// speedup vs baseline: 1.3673x; 1.3673x over previous
#include <cuda_runtime.h>

#define NSTEP  25
#define NIN    9
#define NHID   100

__global__ __launch_bounds__(64) void snn_kernel(
    const float* __restrict__ x,
    const float* __restrict__ W1,
    const float* __restrict__ b1,
    const float* __restrict__ W2,
    const float* __restrict__ b2,
    float* __restrict__ out,
    int batch)
{
    // W1 padded to 12 floats/row: [w0..w8, b1, 0, 0] -> 3x LDS.128 per neuron
    __shared__ float4 sW1[NHID * 3];
    __shared__ float2 sW2[NHID];   // (W2[0][h], W2[1][h])
    __shared__ float  sb2[2];

    {
        float* sW1f = (float*)sW1;
        for (int h = threadIdx.x; h < NHID; h += blockDim.x) {
#pragma unroll
            for (int i = 0; i < NIN; i++) sW1f[h * 12 + i] = W1[h * NIN + i];
            sW1f[h * 12 + 9]  = b1[h];
            sW1f[h * 12 + 10] = 0.0f;
            sW1f[h * 12 + 11] = 0.0f;
            sW2[h] = make_float2(W2[h], W2[NHID + h]);
        }
        if (threadIdx.x < 2) sb2[threadIdx.x] = b2[threadIdx.x];
    }
    __syncthreads();

    int b = blockIdx.x * blockDim.x + threadIdx.x;
    if (b >= batch) return;

    float xv[NIN];
#pragma unroll
    for (int i = 0; i < NIN; i++) xv[i] = __ldg(&x[(size_t)b * NIN + i]);

    float acc0[NSTEP], acc1[NSTEP];
#pragma unroll
    for (int t = 0; t < NSTEP; t++) { acc0[t] = 0.0f; acc1[t] = 0.0f; }

    // 4 hidden neurons per iteration: 4 independent 8-cycle recurrence chains,
    // 20 instructions per step window -> issue-saturating ILP.
    for (int h = 0; h < NHID; h += 4) {
        float c[4];
#pragma unroll
        for (int j = 0; j < 4; j++) {
            float4 a0 = sW1[(h + j) * 3 + 0];
            float4 a1 = sW1[(h + j) * 3 + 1];
            float4 a2 = sW1[(h + j) * 3 + 2];
            float cc = a2.y;                       // bias in padded slot 9
            cc = fmaf(xv[0], a0.x, cc); cc = fmaf(xv[1], a0.y, cc);
            cc = fmaf(xv[2], a0.z, cc); cc = fmaf(xv[3], a0.w, cc);
            cc = fmaf(xv[4], a1.x, cc); cc = fmaf(xv[5], a1.y, cc);
            cc = fmaf(xv[6], a1.z, cc); cc = fmaf(xv[7], a1.w, cc);
            cc = fmaf(xv[8], a2.x, cc);
            c[j] = cc;
        }
        float2 w0 = sW2[h], w1 = sW2[h + 1], w2 = sW2[h + 2], w3 = sW2[h + 3];

        float m0 = 0.f, m1 = 0.f, m2 = 0.f, m3 = 0.f;   // membranes
        float r0 = 0.f, r1 = 0.f, r2 = 0.f, r3 = 0.f;   // spikes (float 0/1)

        // Per neuron-step (5 instr): FFMA-imm, FADD, FSET, FFMA, FFMA
        //   m   = beta*m + c - r_prev     (reset from previous step's spike)
        //   r   = (m > 1) ? 1.0 : 0.0     (FSET: alu, pred-free)
        //   acc += r * w2cols
#pragma unroll
        for (int t = 0; t < NSTEP; t++) {
            m0 = fmaf(0.95f, m0, c[0]) - r0;
            m1 = fmaf(0.95f, m1, c[1]) - r1;
            m2 = fmaf(0.95f, m2, c[2]) - r2;
            m3 = fmaf(0.95f, m3, c[3]) - r3;
            asm("set.gt.f32.f32 %0, %1, 0f3F800000;" : "=f"(r0) : "f"(m0));
            asm("set.gt.f32.f32 %0, %1, 0f3F800000;" : "=f"(r1) : "f"(m1));
            asm("set.gt.f32.f32 %0, %1, 0f3F800000;" : "=f"(r2) : "f"(m2));
            asm("set.gt.f32.f32 %0, %1, 0f3F800000;" : "=f"(r3) : "f"(m3));
            acc0[t] = fmaf(r0, w0.x, acc0[t]);  acc1[t] = fmaf(r0, w0.y, acc1[t]);
            acc0[t] = fmaf(r1, w1.x, acc0[t]);  acc1[t] = fmaf(r1, w1.y, acc1[t]);
            acc0[t] = fmaf(r2, w2.x, acc0[t]);  acc1[t] = fmaf(r2, w2.y, acc1[t]);
            acc0[t] = fmaf(r3, w3.x, acc0[t]);  acc1[t] = fmaf(r3, w3.y, acc1[t]);
        }
    }

    // Layer-2 LIF recurrence + record mem2 each step
    const float bb0 = sb2[0], bb1 = sb2[1];
    float m20 = 0.0f, m21 = 0.0f;
    float2* outv = (float2*)out;
#pragma unroll
    for (int t = 0; t < NSTEP; t++) {
        float rr0, rr1;                               // reset from PREVIOUS mem2
        asm("set.gt.f32.f32 %0, %1, 0f3F800000;" : "=f"(rr0) : "f"(m20));
        asm("set.gt.f32.f32 %0, %1, 0f3F800000;" : "=f"(rr1) : "f"(m21));
        m20 = fmaf(0.95f, m20, acc0[t] + bb0) - rr0;
        m21 = fmaf(0.95f, m21, acc1[t] + bb1) - rr1;
        outv[(size_t)t * batch + b] = make_float2(m20, m21);
    }
}

extern "C" void kernel_launch(void* const* d_in, const int* in_sizes, int n_in,
                              void* d_out, int out_size)
{
    const float* x  = (const float*)d_in[0];
    const float* W1 = (const float*)d_in[1];
    const float* b1 = (const float*)d_in[2];
    const float* W2 = (const float*)d_in[3];
    const float* b2 = (const float*)d_in[4];
    float* out = (float*)d_out;

    int batch = in_sizes[0] / NIN;
    const int threads = 64;
    int blocks = (batch + threads - 1) / threads;
    snn_kernel<<<blocks, threads>>>(x, W1, b1, W2, b2, out, batch);
}